// round 16
// baseline (speedup 1.0000x reference)
#include <cuda_runtime.h>

// Model: GRU-D, B=512, T=512, V=64, H=128, C=4, 3 stacked GRU layers + softmax head.
// Batch-partitioned persistent kernel: 128 CTAs x 4 batch rows, 384 threads
// (one thread per gate row j in [0,384)). Hidden states + current input live in
// SMEM; weights streamed from L2 each step (coalesced float4, one read per CTA
// per step, reused across the 4 batch rows).

#define Bb  512
#define Tt  512
#define Vv  64
#define Hh  128
#define G3  384      // 3*H
#define Cc  4
#define MB  4
#define NBLK (Bb / MB)   // 128
#define NTH  384

__device__ __forceinline__ float sigm(float v) {
    return 1.0f / (1.0f + __expf(-v));
}

// Computes, for this thread's gate row j:
//   gi[m][j] = bih[j] + dot(in[m][:DIN],  Wih[j][:DIN])
//   gh[m][j] = bhh[j] + dot(hs[m][:H],    Whh[j][:H])
// for m = 0..3. Weight rows loaded once (float4), reused across the 4 rows.
template<int DIN>
__device__ __forceinline__ void gate_matmul(
    const float* __restrict__ in,   // SMEM [MB][DIN]
    const float* __restrict__ hs,   // SMEM [MB][Hh]
    const float* __restrict__ Wih,  // GMEM [G3][DIN]
    const float* __restrict__ Whh,  // GMEM [G3][Hh]
    const float* __restrict__ bih,
    const float* __restrict__ bhh,
    float* __restrict__ gi,         // SMEM [MB][G3]
    float* __restrict__ gh,         // SMEM [MB][G3]
    int j)
{
    // ---- input-gate part ----
    {
        const float4* w  = reinterpret_cast<const float4*>(Wih + j * DIN);
        const float4* v0 = reinterpret_cast<const float4*>(in);
        const float4* v1 = reinterpret_cast<const float4*>(in + DIN);
        const float4* v2 = reinterpret_cast<const float4*>(in + 2 * DIN);
        const float4* v3 = reinterpret_cast<const float4*>(in + 3 * DIN);
        float a0 = 0.f, a1 = 0.f, a2 = 0.f, a3 = 0.f;
#pragma unroll
        for (int kb = 0; kb < DIN / 4; ++kb) {
            float4 ww = w[kb];
            float4 p;
            p = v0[kb]; a0 = fmaf(ww.x, p.x, fmaf(ww.y, p.y, fmaf(ww.z, p.z, fmaf(ww.w, p.w, a0))));
            p = v1[kb]; a1 = fmaf(ww.x, p.x, fmaf(ww.y, p.y, fmaf(ww.z, p.z, fmaf(ww.w, p.w, a1))));
            p = v2[kb]; a2 = fmaf(ww.x, p.x, fmaf(ww.y, p.y, fmaf(ww.z, p.z, fmaf(ww.w, p.w, a2))));
            p = v3[kb]; a3 = fmaf(ww.x, p.x, fmaf(ww.y, p.y, fmaf(ww.z, p.z, fmaf(ww.w, p.w, a3))));
        }
        float b = bih[j];
        gi[0 * G3 + j] = a0 + b;
        gi[1 * G3 + j] = a1 + b;
        gi[2 * G3 + j] = a2 + b;
        gi[3 * G3 + j] = a3 + b;
    }
    // ---- hidden-gate part ----
    {
        const float4* w  = reinterpret_cast<const float4*>(Whh + j * Hh);
        const float4* v0 = reinterpret_cast<const float4*>(hs);
        const float4* v1 = reinterpret_cast<const float4*>(hs + Hh);
        const float4* v2 = reinterpret_cast<const float4*>(hs + 2 * Hh);
        const float4* v3 = reinterpret_cast<const float4*>(hs + 3 * Hh);
        float a0 = 0.f, a1 = 0.f, a2 = 0.f, a3 = 0.f;
#pragma unroll
        for (int kb = 0; kb < Hh / 4; ++kb) {
            float4 ww = w[kb];
            float4 p;
            p = v0[kb]; a0 = fmaf(ww.x, p.x, fmaf(ww.y, p.y, fmaf(ww.z, p.z, fmaf(ww.w, p.w, a0))));
            p = v1[kb]; a1 = fmaf(ww.x, p.x, fmaf(ww.y, p.y, fmaf(ww.z, p.z, fmaf(ww.w, p.w, a1))));
            p = v2[kb]; a2 = fmaf(ww.x, p.x, fmaf(ww.y, p.y, fmaf(ww.z, p.z, fmaf(ww.w, p.w, a2))));
            p = v3[kb]; a3 = fmaf(ww.x, p.x, fmaf(ww.y, p.y, fmaf(ww.z, p.z, fmaf(ww.w, p.w, a3))));
        }
        float b = bhh[j];
        gh[0 * G3 + j] = a0 + b;
        gh[1 * G3 + j] = a1 + b;
        gh[2 * G3 + j] = a2 + b;
        gh[3 * G3 + j] = a3 + b;
    }
}

// GRU elementwise update: h <- (1-z)*n + z*h
__device__ __forceinline__ void gru_update(
    const float* __restrict__ gi,   // SMEM [MB][G3]
    const float* __restrict__ gh,   // SMEM [MB][G3]
    float* __restrict__ hs,         // SMEM [MB][Hh]
    int tid)
{
#pragma unroll
    for (int idx = tid; idx < MB * Hh; idx += NTH) {
        int m = idx >> 7;
        int h = idx & (Hh - 1);
        const float* gim = gi + m * G3;
        const float* ghm = gh + m * G3;
        float r = sigm(gim[h] + ghm[h]);
        float z = sigm(gim[Hh + h] + ghm[Hh + h]);
        float n = tanhf(gim[2 * Hh + h] + r * ghm[2 * Hh + h]);
        float ho = hs[m * Hh + h];
        hs[m * Hh + h] = (1.0f - z) * n + z * ho;
    }
}

__global__ __launch_bounds__(NTH)
void grud_kernel(
    const float* __restrict__ x,     const float* __restrict__ d,     const float* __restrict__ m1,
    const float* __restrict__ h0_1,  const float* __restrict__ h0_2,  const float* __restrict__ h0_3,
    const float* __restrict__ W_ih1, const float* __restrict__ W_hh1, const float* __restrict__ b_ih1, const float* __restrict__ b_hh1,
    const float* __restrict__ W_ih2, const float* __restrict__ W_hh2, const float* __restrict__ b_ih2, const float* __restrict__ b_hh2,
    const float* __restrict__ W_ih3, const float* __restrict__ W_hh3, const float* __restrict__ b_ih3, const float* __restrict__ b_hh3,
    const float* __restrict__ W_out, const float* __restrict__ b_out,
    const float* __restrict__ W_dx,  const float* __restrict__ b_dx,
    const float* __restrict__ W_dh,  const float* __restrict__ b_dh,
    float* __restrict__ out)
{
    __shared__ float sx0[MB * Vv];        // x[:,0,:]  (fixed)
    __shared__ float sx1[MB * Vv];        // current x1 input
    __shared__ float sh1[MB * Hh];
    __shared__ float sh2[MB * Hh];
    __shared__ float sh3[MB * Hh];
    __shared__ float sgi[MB * G3];
    __shared__ float sgh[MB * G3];
    __shared__ float slog[MB * Cc];

    const int tid = threadIdx.x;
    const int b0  = blockIdx.x * MB;

    // ---- init: x0 and h0 ----
    for (int idx = tid; idx < MB * Vv; idx += NTH) {
        int m = idx >> 6;
        int v = idx & (Vv - 1);
        float xv = x[(size_t)(b0 + m) * Tt * Vv + v];   // t = 0
        sx0[idx] = xv;
        sx1[idx] = xv;
        (void)m;
    }
    for (int idx = tid; idx < MB * Hh; idx += NTH) {
        int m = idx >> 7;
        int h = idx & (Hh - 1);
        sh1[idx] = h0_1[(b0 + m) * Hh + h];
        sh2[idx] = h0_2[(b0 + m) * Hh + h];
        sh3[idx] = h0_3[(b0 + m) * Hh + h];
    }
    __syncthreads();

    for (int t = 0; t < Tt; ++t) {
        if (t > 0) {
            // ---- decay hidden states: h *= exp(-relu(d*W_dh + b_dh)) ----
            for (int idx = tid; idx < MB * Hh; idx += NTH) {
                int m = idx >> 7;
                int h = idx & (Hh - 1);
                float dt = d[(size_t)(b0 + m) * Tt + t];
                float e  = fmaf(dt, W_dh[h], b_dh[h]);
                float g  = __expf(-fmaxf(e, 0.0f));
                sh1[idx] *= g;
                sh2[idx] *= g;
                sh3[idx] *= g;
            }
            // ---- masked / decayed input imputation ----
            for (int idx = tid; idx < MB * Vv; idx += NTH) {
                int m = idx >> 6;
                int v = idx & (Vv - 1);
                size_t base = (size_t)(b0 + m) * Tt * Vv + (size_t)t * Vv + v;
                float dt = d[(size_t)(b0 + m) * Tt + t];
                float e  = fmaf(dt, W_dx[v], b_dx[v]);
                float gx = __expf(-fmaxf(e, 0.0f));
                float xt = x[base];
                float xp = x[base - Vv];
                float mt = m1[base];
                float imput = xp * gx + (1.0f - gx) * sx0[idx];
                sx1[idx] = imput * (1.0f - mt) + mt * xt;
            }
            __syncthreads();
        }

        // ---- layer 1 ----
        gate_matmul<Vv>(sx1, sh1, W_ih1, W_hh1, b_ih1, b_hh1, sgi, sgh, tid);
        __syncthreads();
        gru_update(sgi, sgh, sh1, tid);
        __syncthreads();

        // ---- layer 2 ----
        gate_matmul<Hh>(sh1, sh2, W_ih2, W_hh2, b_ih2, b_hh2, sgi, sgh, tid);
        __syncthreads();
        gru_update(sgi, sgh, sh2, tid);
        __syncthreads();

        // ---- layer 3 ----
        gate_matmul<Hh>(sh2, sh3, W_ih3, W_hh3, b_ih3, b_hh3, sgi, sgh, tid);
        __syncthreads();
        gru_update(sgi, sgh, sh3, tid);
        __syncthreads();

        // ---- head: logits ----
        if (tid < MB * Cc) {
            int m = tid / Cc;
            int c = tid % Cc;
            const float4* wo = reinterpret_cast<const float4*>(W_out + c * Hh);
            const float4* hv = reinterpret_cast<const float4*>(sh3 + m * Hh);
            float s = b_out[c];
#pragma unroll
            for (int kb = 0; kb < Hh / 4; ++kb) {
                float4 w = wo[kb];
                float4 v = hv[kb];
                s = fmaf(w.x, v.x, fmaf(w.y, v.y, fmaf(w.z, v.z, fmaf(w.w, v.w, s))));
            }
            slog[m * Cc + c] = s;
        }
        __syncthreads();

        // ---- softmax + store ----
        if (tid < MB) {
            int m = tid;
            float l0 = slog[m * Cc + 0];
            float l1 = slog[m * Cc + 1];
            float l2 = slog[m * Cc + 2];
            float l3 = slog[m * Cc + 3];
            float mx = fmaxf(fmaxf(l0, l1), fmaxf(l2, l3));
            float e0 = __expf(l0 - mx);
            float e1 = __expf(l1 - mx);
            float e2 = __expf(l2 - mx);
            float e3 = __expf(l3 - mx);
            float inv = 1.0f / (e0 + e1 + e2 + e3);
            float4 o;
            o.x = e0 * inv; o.y = e1 * inv; o.z = e2 * inv; o.w = e3 * inv;
            reinterpret_cast<float4*>(out + ((size_t)(b0 + m) * Tt + t) * Cc)[0] = o;
        }
        // No sync needed here: next iteration's writers (decay phase) touch only
        // sh*/sx1, whose last readers finished before the preceding barrier;
        // slog is next written only after several more barriers.
    }
}

extern "C" void kernel_launch(void* const* d_in, const int* in_sizes, int n_in,
                              void* d_out, int out_size) {
    (void)in_sizes; (void)n_in; (void)out_size;
    grud_kernel<<<NBLK, NTH>>>(
        (const float*)d_in[0],  (const float*)d_in[1],  (const float*)d_in[2],
        (const float*)d_in[3],  (const float*)d_in[4],  (const float*)d_in[5],
        (const float*)d_in[6],  (const float*)d_in[7],  (const float*)d_in[8],  (const float*)d_in[9],
        (const float*)d_in[10], (const float*)d_in[11], (const float*)d_in[12], (const float*)d_in[13],
        (const float*)d_in[14], (const float*)d_in[15], (const float*)d_in[16], (const float*)d_in[17],
        (const float*)d_in[18], (const float*)d_in[19],
        (const float*)d_in[20], (const float*)d_in[21],
        (const float*)d_in[22], (const float*)d_in[23],
        (float*)d_out);
}

// round 17
// speedup vs baseline: 4.4592x; 4.4592x over previous
#include <cuda_runtime.h>

// GRU-D: B=512, T=512, V=64, H=128, C=4, 3 GRU layers + softmax head.
// R16: (1) weights pre-transposed to [k/4][j][4] so weight loads are fully
// coalesced (was 32 L1 wavefronts per LDG.128 -> now 4).
// (2) batch rows processed in packed f32x2 pairs via PTX fma.rn.f32x2
// (2x fp32 throughput; ptxas never emits FFMA2 from C++).
// 128 persistent CTAs x 4 batch rows, 384 threads = one thread per gate row j.

#define Bb  512
#define Tt  512
#define Vv  64
#define Hh  128
#define G3  384
#define Cc  4
#define MB  4
#define NBLK (Bb / MB)
#define NTH  384

typedef unsigned long long ull;

// Transposed-weight scratch: 270336 floats = 67584 float4 (16B-aligned).
__device__ float4 g_WT[67584];

// float4-unit offsets of each matrix inside g_WT
#define OFF_IH1 0
#define OFF_HH1 6144
#define OFF_IH2 18432
#define OFF_HH2 30720
#define OFF_IH3 43008
#define OFF_HH3 55296

// dst[(k>>2)*(G3*4) + j*4 + (k&3)] = W[j*DIN + k]
__global__ void transpose_w(const float* __restrict__ W, int DIN, int off4) {
    float* dst = reinterpret_cast<float*>(g_WT) + (size_t)off4 * 4;
    int n = G3 * DIN;
    for (int idx = blockIdx.x * blockDim.x + threadIdx.x; idx < n;
         idx += gridDim.x * blockDim.x) {
        int j = idx / DIN;
        int k = idx - j * DIN;
        dst[(k >> 2) * (G3 * 4) + j * 4 + (k & 3)] = W[idx];
    }
}

// ---- packed f32x2 helpers ----
__device__ __forceinline__ ull pk2(float a, float b) {
    ull r; asm("mov.b64 %0, {%1, %2};" : "=l"(r) : "f"(a), "f"(b)); return r;
}
__device__ __forceinline__ ull fma2(ull a, ull b, ull c) {
    ull d; asm("fma.rn.f32x2 %0, %1, %2, %3;" : "=l"(d) : "l"(a), "l"(b), "l"(c));
    return d;
}
__device__ __forceinline__ float2 upk2(ull a) {
    float2 r; asm("mov.b64 {%0, %1}, %2;" : "=f"(r.x), "=f"(r.y) : "l"(a)); return r;
}
__device__ __forceinline__ float sigm(float v) { return 1.0f / (1.0f + __expf(-v)); }

// acc01/acc23 = packed dot products of weight row j with the pair-interleaved
// input vectors (pair0 = batch rows 0,1; pair1 = rows 2,3).
// WT layout: float4 index kb*G3 + j. inP layout: ulonglong2 index k/2 holding
// packed pairs for k and k+1.
template<int DIN>
__device__ __forceinline__ void mm(const float4* __restrict__ WT,
                                   const ulonglong2* __restrict__ in01,
                                   const ulonglong2* __restrict__ in23,
                                   ull& acc01, ull& acc23, int j)
{
    ull a01 = 0ull, a23 = 0ull;
#pragma unroll 4
    for (int kb = 0; kb < DIN / 4; ++kb) {
        float4 ww = WT[kb * G3 + j];
        ulonglong2 qa = in01[2 * kb];
        ulonglong2 qb = in01[2 * kb + 1];
        ulonglong2 ra = in23[2 * kb];
        ulonglong2 rb = in23[2 * kb + 1];
        ull wx = pk2(ww.x, ww.x), wy = pk2(ww.y, ww.y);
        ull wz = pk2(ww.z, ww.z), wv = pk2(ww.w, ww.w);
        a01 = fma2(wx, qa.x, a01);  a23 = fma2(wx, ra.x, a23);
        a01 = fma2(wy, qa.y, a01);  a23 = fma2(wy, ra.y, a23);
        a01 = fma2(wz, qb.x, a01);  a23 = fma2(wz, rb.x, a23);
        a01 = fma2(wv, qb.y, a01);  a23 = fma2(wv, rb.y, a23);
    }
    acc01 = a01; acc23 = a23;
}

__global__ __launch_bounds__(NTH, 1)
void grud_kernel(
    const float* __restrict__ x,     const float* __restrict__ d,     const float* __restrict__ m1,
    const float* __restrict__ h0_1,  const float* __restrict__ h0_2,  const float* __restrict__ h0_3,
    const float* __restrict__ b_ih1, const float* __restrict__ b_hh1,
    const float* __restrict__ b_ih2, const float* __restrict__ b_hh2,
    const float* __restrict__ b_ih3, const float* __restrict__ b_hh3,
    const float* __restrict__ W_out, const float* __restrict__ b_out,
    const float* __restrict__ W_dx,  const float* __restrict__ b_dx,
    const float* __restrict__ W_dh,  const float* __restrict__ b_dh,
    float* __restrict__ out)
{
    // pair-interleaved state: [pair][k/2] float4 = (mA[k], mB[k], mA[k+1], mB[k+1])
    __shared__ float4 sx0s[2][Vv / 2];
    __shared__ float4 sx1s[2][Vv / 2];
    __shared__ float4 sh1s[2][Hh / 2];
    __shared__ float4 sh2s[2][Hh / 2];
    __shared__ float4 sh3s[2][Hh / 2];
    __shared__ float2 sgi[2][G3];
    __shared__ float2 sgh[2][G3];
    __shared__ float  slog[MB * Cc];

    const int tid = threadIdx.x;
    const int b0  = blockIdx.x * MB;

    const float4* WihT1 = g_WT + OFF_IH1;
    const float4* WhhT1 = g_WT + OFF_HH1;
    const float4* WihT2 = g_WT + OFF_IH2;
    const float4* WhhT2 = g_WT + OFF_HH2;
    const float4* WihT3 = g_WT + OFF_IH3;
    const float4* WhhT3 = g_WT + OFF_HH3;

    // ---- init: x0 and h0 (pair-interleaved) ----
    for (int idx = tid; idx < MB * Vv; idx += NTH) {
        int m = idx >> 6, v = idx & (Vv - 1);
        float xv = x[(size_t)(b0 + m) * Tt * Vv + v];          // t = 0
        int p = m >> 1, ml = m & 1;
        reinterpret_cast<float*>(sx0s[p])[v * 2 + ml] = xv;
        reinterpret_cast<float*>(sx1s[p])[v * 2 + ml] = xv;
    }
    for (int idx = tid; idx < MB * Hh; idx += NTH) {
        int m = idx >> 7, h = idx & (Hh - 1);
        int p = m >> 1, ml = m & 1;
        int gidx = (b0 + m) * Hh + h;
        reinterpret_cast<float*>(sh1s[p])[h * 2 + ml] = h0_1[gidx];
        reinterpret_cast<float*>(sh2s[p])[h * 2 + ml] = h0_2[gidx];
        reinterpret_cast<float*>(sh3s[p])[h * 2 + ml] = h0_3[gidx];
    }
    __syncthreads();

    for (int t = 0; t < Tt; ++t) {
        if (t > 0) {
            // ---- hidden decay: h *= exp(-relu(d*W_dh + b_dh)) ----
            for (int idx = tid; idx < MB * Hh; idx += NTH) {
                int m = idx >> 7, h = idx & (Hh - 1);
                int p = m >> 1, ml = m & 1;
                float dt = d[(size_t)(b0 + m) * Tt + t];
                float g = __expf(-fmaxf(fmaf(dt, W_dh[h], b_dh[h]), 0.0f));
                int off = h * 2 + ml;
                reinterpret_cast<float*>(sh1s[p])[off] *= g;
                reinterpret_cast<float*>(sh2s[p])[off] *= g;
                reinterpret_cast<float*>(sh3s[p])[off] *= g;
            }
            // ---- masked / decayed input imputation ----
            for (int idx = tid; idx < MB * Vv; idx += NTH) {
                int m = idx >> 6, v = idx & (Vv - 1);
                int p = m >> 1, ml = m & 1;
                size_t base = (size_t)(b0 + m) * Tt * Vv + (size_t)t * Vv + v;
                float dt = d[(size_t)(b0 + m) * Tt + t];
                float gx = __expf(-fmaxf(fmaf(dt, W_dx[v], b_dx[v]), 0.0f));
                float xt = x[base];
                float xp = x[base - Vv];
                float mt = m1[base];
                float x0v = reinterpret_cast<const float*>(sx0s[p])[v * 2 + ml];
                float imput = xp * gx + (1.0f - gx) * x0v;
                reinterpret_cast<float*>(sx1s[p])[v * 2 + ml] =
                    imput * (1.0f - mt) + mt * xt;
            }
            __syncthreads();
        }

        const int j = tid;
        ull ai01, ai23, ah01, ah23;
        float2 v2; float b;

        // ---------------- layer 1 ----------------
        mm<Vv>(WihT1, (const ulonglong2*)sx1s[0], (const ulonglong2*)sx1s[1], ai01, ai23, j);
        mm<Hh>(WhhT1, (const ulonglong2*)sh1s[0], (const ulonglong2*)sh1s[1], ah01, ah23, j);
        b = b_ih1[j];
        v2 = upk2(ai01); sgi[0][j] = make_float2(v2.x + b, v2.y + b);
        v2 = upk2(ai23); sgi[1][j] = make_float2(v2.x + b, v2.y + b);
        b = b_hh1[j];
        v2 = upk2(ah01); sgh[0][j] = make_float2(v2.x + b, v2.y + b);
        v2 = upk2(ah23); sgh[1][j] = make_float2(v2.x + b, v2.y + b);
        __syncthreads();
        for (int idx = tid; idx < MB * Hh; idx += NTH) {
            int m = idx >> 7, h = idx & (Hh - 1);
            int p = m >> 1, ml = m & 1;
            const float* gip = (const float*)sgi[p];
            const float* ghp = (const float*)sgh[p];
            float r = sigm(gip[h * 2 + ml] + ghp[h * 2 + ml]);
            float z = sigm(gip[(Hh + h) * 2 + ml] + ghp[(Hh + h) * 2 + ml]);
            float n = tanhf(gip[(2 * Hh + h) * 2 + ml] + r * ghp[(2 * Hh + h) * 2 + ml]);
            float* hp = reinterpret_cast<float*>(sh1s[p]) + h * 2 + ml;
            *hp = (1.0f - z) * n + z * (*hp);
        }
        __syncthreads();

        // ---------------- layer 2 ----------------
        mm<Hh>(WihT2, (const ulonglong2*)sh1s[0], (const ulonglong2*)sh1s[1], ai01, ai23, j);
        mm<Hh>(WhhT2, (const ulonglong2*)sh2s[0], (const ulonglong2*)sh2s[1], ah01, ah23, j);
        b = b_ih2[j];
        v2 = upk2(ai01); sgi[0][j] = make_float2(v2.x + b, v2.y + b);
        v2 = upk2(ai23); sgi[1][j] = make_float2(v2.x + b, v2.y + b);
        b = b_hh2[j];
        v2 = upk2(ah01); sgh[0][j] = make_float2(v2.x + b, v2.y + b);
        v2 = upk2(ah23); sgh[1][j] = make_float2(v2.x + b, v2.y + b);
        __syncthreads();
        for (int idx = tid; idx < MB * Hh; idx += NTH) {
            int m = idx >> 7, h = idx & (Hh - 1);
            int p = m >> 1, ml = m & 1;
            const float* gip = (const float*)sgi[p];
            const float* ghp = (const float*)sgh[p];
            float r = sigm(gip[h * 2 + ml] + ghp[h * 2 + ml]);
            float z = sigm(gip[(Hh + h) * 2 + ml] + ghp[(Hh + h) * 2 + ml]);
            float n = tanhf(gip[(2 * Hh + h) * 2 + ml] + r * ghp[(2 * Hh + h) * 2 + ml]);
            float* hp = reinterpret_cast<float*>(sh2s[p]) + h * 2 + ml;
            *hp = (1.0f - z) * n + z * (*hp);
        }
        __syncthreads();

        // ---------------- layer 3 ----------------
        mm<Hh>(WihT3, (const ulonglong2*)sh2s[0], (const ulonglong2*)sh2s[1], ai01, ai23, j);
        mm<Hh>(WhhT3, (const ulonglong2*)sh3s[0], (const ulonglong2*)sh3s[1], ah01, ah23, j);
        b = b_ih3[j];
        v2 = upk2(ai01); sgi[0][j] = make_float2(v2.x + b, v2.y + b);
        v2 = upk2(ai23); sgi[1][j] = make_float2(v2.x + b, v2.y + b);
        b = b_hh3[j];
        v2 = upk2(ah01); sgh[0][j] = make_float2(v2.x + b, v2.y + b);
        v2 = upk2(ah23); sgh[1][j] = make_float2(v2.x + b, v2.y + b);
        __syncthreads();
        for (int idx = tid; idx < MB * Hh; idx += NTH) {
            int m = idx >> 7, h = idx & (Hh - 1);
            int p = m >> 1, ml = m & 1;
            const float* gip = (const float*)sgi[p];
            const float* ghp = (const float*)sgh[p];
            float r = sigm(gip[h * 2 + ml] + ghp[h * 2 + ml]);
            float z = sigm(gip[(Hh + h) * 2 + ml] + ghp[(Hh + h) * 2 + ml]);
            float n = tanhf(gip[(2 * Hh + h) * 2 + ml] + r * ghp[(2 * Hh + h) * 2 + ml]);
            float* hp = reinterpret_cast<float*>(sh3s[p]) + h * 2 + ml;
            *hp = (1.0f - z) * n + z * (*hp);
        }
        __syncthreads();

        // ---------------- head: logits (warp-parallel) ----------------
        {
            int wid = tid >> 5, lane = tid & 31;
            for (int pair = wid; pair < MB * Cc; pair += NTH / 32) {
                int m = pair >> 2, c = pair & 3;
                int p = m >> 1, ml = m & 1;
                const float* hsrc = (const float*)sh3s[p];
                float s = 0.0f;
#pragma unroll
                for (int i = 0; i < Hh / 32; ++i) {
                    int h = lane + 32 * i;
                    s = fmaf(W_out[c * Hh + h], hsrc[h * 2 + ml], s);
                }
#pragma unroll
                for (int off = 16; off; off >>= 1)
                    s += __shfl_down_sync(0xffffffffu, s, off);
                if (lane == 0) slog[pair] = s + b_out[c];
            }
        }
        __syncthreads();

        // ---------------- softmax + store ----------------
        if (tid < MB) {
            int m = tid;
            float l0 = slog[m * Cc + 0], l1 = slog[m * Cc + 1];
            float l2 = slog[m * Cc + 2], l3 = slog[m * Cc + 3];
            float mx = fmaxf(fmaxf(l0, l1), fmaxf(l2, l3));
            float e0 = __expf(l0 - mx), e1 = __expf(l1 - mx);
            float e2 = __expf(l2 - mx), e3 = __expf(l3 - mx);
            float inv = 1.0f / (e0 + e1 + e2 + e3);
            float4 o; o.x = e0 * inv; o.y = e1 * inv; o.z = e2 * inv; o.w = e3 * inv;
            reinterpret_cast<float4*>(out + ((size_t)(b0 + m) * Tt + t) * Cc)[0] = o;
        }
        // no barrier needed: next-iter writers touch only sh*/sx1 (readers done
        // before the pre-head sync) and slog is rewritten only after >=2 syncs.
    }
}

extern "C" void kernel_launch(void* const* d_in, const int* in_sizes, int n_in,
                              void* d_out, int out_size) {
    (void)in_sizes; (void)n_in; (void)out_size;
    // transpose weights into g_WT (cheap, graph-capturable)
    transpose_w<<<96, 256>>>((const float*)d_in[6],  Vv, OFF_IH1);
    transpose_w<<<192, 256>>>((const float*)d_in[7],  Hh, OFF_HH1);
    transpose_w<<<192, 256>>>((const float*)d_in[10], Hh, OFF_IH2);
    transpose_w<<<192, 256>>>((const float*)d_in[11], Hh, OFF_HH2);
    transpose_w<<<192, 256>>>((const float*)d_in[14], Hh, OFF_IH3);
    transpose_w<<<192, 256>>>((const float*)d_in[15], Hh, OFF_HH3);

    grud_kernel<<<NBLK, NTH>>>(
        (const float*)d_in[0],  (const float*)d_in[1],  (const float*)d_in[2],
        (const float*)d_in[3],  (const float*)d_in[4],  (const float*)d_in[5],
        (const float*)d_in[8],  (const float*)d_in[9],
        (const float*)d_in[12], (const float*)d_in[13],
        (const float*)d_in[16], (const float*)d_in[17],
        (const float*)d_in[18], (const float*)d_in[19],
        (const float*)d_in[20], (const float*)d_in[21],
        (const float*)d_in[22], (const float*)d_in[23],
        (float*)d_out);
}